// round 10
// baseline (speedup 1.0000x reference)
#include <cuda_runtime.h>
#include <cuda_fp16.h>
#include <math.h>
#include <stdint.h>

#define NROWS 16384
#define DDIM  256
#define KCB   8192
#define NRB   128
#define TM    128

#define OFF_Q   16384
#define OFF_ST  (16384 + NROWS*DDIM)
#define OFF_SC  (16384 + 2*NROWS*DDIM)

#define SLOTS 64
#define EPSF  2e-4f

#define TKT 64                    // cols per k-tile
#define DC  64                    // d per stage
#define KSLICE 1024
#define NSL 8
#define NUNITS (NRB * NSL)        // 1024
#define USTAGES 64                // 16 tiles x 4 d-chunks
#define GRID_SCAN 296

#define A_STRIDE 68               // half2 words per d-row (64 + pad), 272B (16B aligned)
#define AW4 (DDIM * A_STRIDE)     // 17408 words
#define B_STRIDE 36               // words per dd-row: 72 halves = 144B (16B aligned!)
#define BW4 (DC * B_STRIDE)       // 2304 words per buffer
#define SMEM_WORDS (AW4 + 3 * BW4 + TM + 8)
#define SMEM_BYTES (SMEM_WORDS * 4)    // 97,824 B -> 2 CTAs/SM

__device__ unsigned d_xt[(size_t)NRB * DDIM * 64];     // [rbi][d][rowpair] half2
__device__ unsigned short d_ct[(size_t)DDIM * KCB];    // [d][col] half
__device__ float  d_epsp[NROWS];
__device__ float  d_hist[KCB];
__device__ int    d_bidx[NROWS];
__device__ int    d_cnt[NROWS];
__device__ int    d_cand[NROWS * SLOTS];
__device__ double d_sqsum;
__device__ int    d_wq;

// ---------------------------------------------------------------------------
__device__ __forceinline__ uint32_t smem_u32(const void* p) {
    uint32_t a;
    asm("{ .reg .u64 t; cvta.to.shared.u64 t, %1; cvt.u32.u64 %0, t; }" : "=r"(a) : "l"(p));
    return a;
}
__device__ __forceinline__ void cp_async16(uint32_t dst, const void* src) {
    asm volatile("cp.async.cg.shared.global [%0], [%1], 16;" :: "r"(dst), "l"(src) : "memory");
}
#define CP_COMMIT() asm volatile("cp.async.commit_group;" ::: "memory")
#define CP_WAIT(n)  asm volatile("cp.async.wait_group %0;" :: "n"(n) : "memory")

__device__ __forceinline__ int   fmap(float f)  { int i = __float_as_int(f); return i < 0 ? i ^ 0x7FFFFFFF : i; }
__device__ __forceinline__ float funmap(int u)  { if (u < 0) u ^= 0x7FFFFFFF; return __int_as_float(u); }

// ---------------------------------------------------------------------------
// Kernel 1: zero accumulators + work queue
// ---------------------------------------------------------------------------
__global__ void k_init() {
    int i = blockIdx.x * 256 + threadIdx.x;
    if (i < KCB)   d_hist[i] = 0.f;
    if (i < NROWS) d_cnt[i]  = 0;
    if (i == 0)  { d_sqsum   = 0.0; d_wq = 0; }
}

// ---------------------------------------------------------------------------
// Kernel 2a: latents -> fp16, per-row scale, transposed [rbi][d][rowpair]
// ---------------------------------------------------------------------------
__global__ __launch_bounds__(256) void k_quant_x(const float* __restrict__ lat) {
    const int tid = threadIdx.x, lane = tid & 31, w = tid >> 5;
    const int row = blockIdx.x * 8 + w;
    const float4* xr = (const float4*)(lat + (size_t)row * DDIM);
    float4 a = xr[lane * 2], b = xr[lane * 2 + 1];
    float v[8] = {a.x, a.y, a.z, a.w, b.x, b.y, b.z, b.w};
    float mx = 0.f;
#pragma unroll
    for (int i = 0; i < 8; i++) mx = fmaxf(mx, fabsf(v[i]));
#pragma unroll
    for (int o = 16; o; o >>= 1) mx = fmaxf(mx, __shfl_xor_sync(0xffffffffu, mx, o));
    float inv = 1.f / fmaxf(mx, 1e-20f);

    unsigned short* xt16 = (unsigned short*)d_xt;
    const int rbi = row >> 7, rp = (row & 127) >> 1, par = row & 1;
#pragma unroll
    for (int i = 0; i < 8; i++) {
        int d = lane * 8 + i;
        xt16[(((size_t)rbi * DDIM + d) * 64 + rp) * 2 + par] =
            __half_as_ushort(__float2half_rn(v[i] * inv));
    }
    if (lane == 0) d_epsp[row] = EPSF * 8192.f * inv;
}

// ---------------------------------------------------------------------------
// Kernel 2b: codebook -> fp16 half, transposed [d][col]
// ---------------------------------------------------------------------------
__global__ __launch_bounds__(256) void k_quant_c(const float* __restrict__ cb) {
    int g = blockIdx.x * 256 + threadIdx.x;        // 2M elements
    int col = g & (KCB - 1), d = g >> 13;
    d_ct[(size_t)d * KCB + col] =
        __half_as_ushort(__float2half_rn(cb[(size_t)col * DDIM + d] * 8192.f));
}

// ---------------------------------------------------------------------------
// Kernel 3: persistent work-queue HFMA2 scan (lean)
// unit = 128 rows x 1024 codes; 256 threads; 2 CTAs/SM
// thread tile: 8 rows (4 half2 pairs) x 4 cols; full-K fp16 accumulation
// ---------------------------------------------------------------------------
#define ISSUE_B(s_) do {                                                         \
    int t_ = (s_) >> 2, c_ = (s_) & 3, buf_ = (s_) % 3;                          \
    const unsigned short* gB_ = d_ct + (size_t)(c_ * DC) * KCB + ksl * KSLICE + t_ * TKT; \
    _Pragma("unroll")                                                            \
    for (int i_ = 0; i_ < 2; i_++) {                                             \
        int s2_ = tid + i_ * 256;                                                \
        int dd_ = s2_ >> 3, ch_ = s2_ & 7;                                       \
        cp_async16(sbB + (uint32_t)(buf_ * (BW4 * 4) + dd_ * (B_STRIDE * 4) + ch_ * 16), \
                   gB_ + (size_t)dd_ * KCB + ch_ * 8);                           \
    }                                                                            \
    CP_COMMIT();                                                                 \
} while (0)

__global__ __launch_bounds__(256, 2) void k_scan_h2() {
    extern __shared__ __align__(16) unsigned smu[];
    unsigned* As = smu;
    unsigned* Bs = smu + AW4;
    int* Rb = (int*)(smu + AW4 + 3 * BW4);
    __shared__ int s_unit;

    const int tid = threadIdx.x;
    const int tx = tid & 15, ty = tid >> 4;
    const uint32_t sbA = smem_u32(As);
    const uint32_t sbB = smem_u32(Bs);

    int cur_rb = -1;
    float epr[8];

    for (;;) {
        if (tid == 0) s_unit = atomicAdd(&d_wq, 1);
        __syncthreads();
        const int u = s_unit;
        if (u >= NUNITS) break;
        const int rbi = u >> 3, ksl = u & 7;
        const int rowblk = rbi * TM;

        if (rbi != cur_rb) {
            const unsigned* gA = d_xt + (size_t)rbi * (DDIM * 64);
#pragma unroll
            for (int i = 0; i < 16; i++) {
                int s2 = tid + i * 256;
                int d = s2 >> 4, rpg = s2 & 15;
                cp_async16(sbA + (uint32_t)(d * A_STRIDE + rpg * 4) * 4,
                           gA + (size_t)d * 64 + rpg * 4);
            }
            CP_COMMIT();
            if (tid < TM) Rb[tid] = fmap(-3.0e38f);
#pragma unroll
            for (int rr = 0; rr < 8; rr++) epr[rr] = d_epsp[rowblk + ty * 8 + rr];
            cur_rb = rbi;
        }

        ISSUE_B(0);
        ISSUE_B(1);

        __half2 acc[4][4];
#pragma unroll
        for (int p = 0; p < 4; p++)
#pragma unroll
            for (int j = 0; j < 4; j++) acc[p][j] = __float2half2_rn(0.f);

        for (int s = 0; s < USTAGES; s++) {
            const int c = s & 3;
            const unsigned* B = Bs + (s % 3) * BW4;
            if (s + 2 < USTAGES) { CP_WAIT(1); } else { CP_WAIT(0); }
            __syncthreads();
            if (s + 2 < USTAGES) ISSUE_B(s + 2);

#pragma unroll 8
            for (int dd = 0; dd < DC; dd++) {
                uint4 av = *(const uint4*)(As + (size_t)(c * DC + dd) * A_STRIDE + ty * 4);
                __half2 a0 = *(__half2*)&av.x, a1 = *(__half2*)&av.y;
                __half2 a2 = *(__half2*)&av.z, a3 = *(__half2*)&av.w;
                uint2 bv = *(const uint2*)(B + (size_t)dd * B_STRIDE + tx * 2);
                __half2 b01 = *(__half2*)&bv.x, b23 = *(__half2*)&bv.y;
                __half2 d0 = __low2half2(b01),  d1 = __high2half2(b01);
                __half2 d2 = __low2half2(b23),  d3 = __high2half2(b23);
                acc[0][0] = __hfma2(a0, d0, acc[0][0]);
                acc[1][0] = __hfma2(a1, d0, acc[1][0]);
                acc[2][0] = __hfma2(a2, d0, acc[2][0]);
                acc[3][0] = __hfma2(a3, d0, acc[3][0]);
                acc[0][1] = __hfma2(a0, d1, acc[0][1]);
                acc[1][1] = __hfma2(a1, d1, acc[1][1]);
                acc[2][1] = __hfma2(a2, d1, acc[2][1]);
                acc[3][1] = __hfma2(a3, d1, acc[3][1]);
                acc[0][2] = __hfma2(a0, d2, acc[0][2]);
                acc[1][2] = __hfma2(a1, d2, acc[1][2]);
                acc[2][2] = __hfma2(a2, d2, acc[2][2]);
                acc[3][2] = __hfma2(a3, d2, acc[3][2]);
                acc[0][3] = __hfma2(a0, d3, acc[0][3]);
                acc[1][3] = __hfma2(a1, d3, acc[1][3]);
                acc[2][3] = __hfma2(a2, d3, acc[2][3]);
                acc[3][3] = __hfma2(a3, d3, acc[3][3]);
            }

            if (c == 3) {   // end of 64-col k-tile: convert, max, collect, reset
                const int kbase = ksl * KSLICE + (s >> 2) * TKT;
                float vals[8][4];
#pragma unroll
                for (int p = 0; p < 4; p++)
#pragma unroll
                    for (int j = 0; j < 4; j++) {
                        float2 f = __half22float2(acc[p][j]);
                        vals[2 * p + 0][j] = f.x;
                        vals[2 * p + 1][j] = f.y;
                        acc[p][j] = __float2half2_rn(0.f);
                    }
#pragma unroll
                for (int rr = 0; rr < 8; rr++) {
                    float mx = fmaxf(fmaxf(vals[rr][0], vals[rr][1]),
                                     fmaxf(vals[rr][2], vals[rr][3]));
                    mx = fmaxf(mx, __shfl_xor_sync(0xffffffffu, mx, 1));
                    mx = fmaxf(mx, __shfl_xor_sync(0xffffffffu, mx, 2));
                    mx = fmaxf(mx, __shfl_xor_sync(0xffffffffu, mx, 4));
                    mx = fmaxf(mx, __shfl_xor_sync(0xffffffffu, mx, 8));
                    if (tx == 0) {
                        int mm = fmap(mx);
                        if (mm > Rb[ty * 8 + rr]) atomicMax(&Rb[ty * 8 + rr], mm);
                    }
                    // threshold: own tile max always known; Rb stale reads only over-collect
                    const float thr = fmaxf(funmap(Rb[ty * 8 + rr]), mx) - epr[rr];
                    const int grow = rowblk + ty * 8 + rr;
#pragma unroll
                    for (int j = 0; j < 4; j++) {
                        if (vals[rr][j] > thr) {
                            int pos = atomicAdd(&d_cnt[grow], 1);
                            if (pos < SLOTS)
                                d_cand[grow * SLOTS + pos] = kbase + tx * 4 + j;
                        }
                    }
                }
            }
        }
    }
}

// ---------------------------------------------------------------------------
// Kernel 4: exact re-evaluation of candidates, replicate reference rounding:
// q = fl( fl(xn2 + cn2) - 2*dot_f ), argmin with lowest-index ties.
// ---------------------------------------------------------------------------
__global__ __launch_bounds__(256) void k_exact(const float* __restrict__ lat,
                                               const float* __restrict__ cb,
                                               float* __restrict__ out) {
    const int tid = threadIdx.x;
    const int lane = tid & 31, w = tid >> 5;
    const int row = blockIdx.x * 8 + w;

    float x[8];
    {
        const float4* xr = (const float4*)(lat + (size_t)row * DDIM);
        float4 a = xr[lane * 2], b = xr[lane * 2 + 1];
        x[0]=a.x; x[1]=a.y; x[2]=a.z; x[3]=a.w;
        x[4]=b.x; x[5]=b.y; x[6]=b.z; x[7]=b.w;
    }
    double xs = 0.0;
#pragma unroll
    for (int i = 0; i < 8; i++) xs += (double)x[i] * (double)x[i];
#pragma unroll
    for (int o = 16; o; o >>= 1) xs += __shfl_xor_sync(0xffffffffu, xs, o);
    float xn2 = (float)xs;

    int   n     = d_cnt[row];
    bool  fallb = (n > SLOTS);
    int   ncand = fallb ? KCB : n;

    float bestq = 3.4e38f;
    int   besti = 0;

    for (int c = 0; c < ncand; c++) {
        int idx = fallb ? c : d_cand[row * SLOTS + c];
        const float4* cr = (const float4*)(cb + (size_t)idx * DDIM);
        float4 a = cr[lane * 2], b = cr[lane * 2 + 1];
        float cv[8] = {a.x, a.y, a.z, a.w, b.x, b.y, b.z, b.w};

        float hi = 0.f, co = 0.f, cn = 0.f;
#pragma unroll
        for (int i = 0; i < 8; i++) {
            float p = __fmul_rn(x[i], cv[i]);
            float e = __fmaf_rn(x[i], cv[i], -p);
            float t = __fadd_rn(hi, p);
            float z = __fsub_rn(t, hi);
            float q2 = __fadd_rn(__fsub_rn(hi, __fsub_rn(t, z)), __fsub_rn(p, z));
            hi = t; co = __fadd_rn(co, __fadd_rn(q2, e));
            cn = __fmaf_rn(cv[i], cv[i], cn);
        }
#pragma unroll
        for (int o = 16; o; o >>= 1) {
            float h2 = __shfl_xor_sync(0xffffffffu, hi, o);
            float c2 = __shfl_xor_sync(0xffffffffu, co, o);
            cn += __shfl_xor_sync(0xffffffffu, cn, o);
            float t = __fadd_rn(hi, h2);
            float z = __fsub_rn(t, hi);
            float q2 = __fadd_rn(__fsub_rn(hi, __fsub_rn(t, z)), __fsub_rn(h2, z));
            hi = t; co = __fadd_rn(co, __fadd_rn(c2, q2));
        }
        if (lane == 0) {
            float df = __fadd_rn(hi, co);
            float t1 = __fadd_rn(xn2, cn);
            float q  = __fadd_rn(t1, -__fmul_rn(2.f, df));
            if (q < bestq || (q == bestq && idx < besti)) { bestq = q; besti = idx; }
        }
    }
    if (lane == 0) {
        d_bidx[row] = besti;
        out[row] = (float)besti;
    }
}

// ---------------------------------------------------------------------------
// Kernel 5: gather -> quantized + st_quantized, MSE partials, histogram
// ---------------------------------------------------------------------------
__global__ __launch_bounds__(256) void k_gather(const float* __restrict__ lat,
                                                const float* __restrict__ mask,
                                                const float* __restrict__ cb,
                                                float* __restrict__ out) {
    __shared__ float wsum[8];
    const int tid = threadIdx.x;
    const int lane = tid & 31, w = tid >> 5;
    const int row = blockIdx.x * 8 + w;

    int idx = d_bidx[row];
    const float4* x = (const float4*)(lat + (size_t)row * DDIM);
    const float4* c = (const float4*)(cb + (size_t)idx * DDIM);
    float4* q  = (float4*)(out + OFF_Q  + (size_t)row * DDIM);
    float4* st = (float4*)(out + OFF_ST + (size_t)row * DDIM);

    float s = 0.f;
#pragma unroll
    for (int i = lane; i < DDIM / 4; i += 32) {
        float4 cv = c[i], xv = x[i];
        q[i]  = cv;
        st[i] = cv;
        float d0 = xv.x - cv.x, d1 = xv.y - cv.y;
        float d2 = xv.z - cv.z, d3 = xv.w - cv.w;
        s += d0 * d0 + d1 * d1 + d2 * d2 + d3 * d3;
    }
#pragma unroll
    for (int o = 16; o; o >>= 1) s += __shfl_xor_sync(0xffffffffu, s, o);
    if (lane == 0) {
        wsum[w] = s;
        atomicAdd(&d_hist[idx], mask[row]);
    }
    __syncthreads();
    if (tid == 0) {
        double t = 0.0;
#pragma unroll
        for (int i = 0; i < 8; i++) t += (double)wsum[i];
        atomicAdd(&d_sqsum, t);
    }
}

// ---------------------------------------------------------------------------
// Kernel 6: finalize losses + perplexity
// ---------------------------------------------------------------------------
__global__ void k_final(const float* __restrict__ mask, float* __restrict__ out) {
    __shared__ float sh[256];
    const int tid = threadIdx.x;

    float m = 0.f;
    for (int i = tid; i < NROWS; i += 256) m += mask[i];
    sh[tid] = m; __syncthreads();
    for (int o = 128; o; o >>= 1) { if (tid < o) sh[tid] += sh[tid + o]; __syncthreads(); }
    float denom = fmaxf(sh[0], 1.0f);
    __syncthreads();

    float e = 0.f;
    for (int k2 = tid; k2 < KCB; k2 += 256) {
        float p = d_hist[k2] / denom;
        e += p * logf(p + 1e-8f);
    }
    sh[tid] = e; __syncthreads();
    for (int o = 128; o; o >>= 1) { if (tid < o) sh[tid] += sh[tid + o]; __syncthreads(); }

    if (tid == 0) {
        double mse = d_sqsum / (double)((size_t)NROWS * DDIM);
        out[OFF_SC + 0] = (float)(mse * 0.25);
        out[OFF_SC + 1] = (float)mse;
        out[OFF_SC + 2] = expf(-sh[0]);
    }
}

// ---------------------------------------------------------------------------
extern "C" void kernel_launch(void* const* d_in, const int* in_sizes, int n_in,
                              void* d_out, int out_size) {
    const float* lat  = (const float*)d_in[0];
    const float* mask = (const float*)d_in[1];
    const float* cb   = (const float*)d_in[2];
    float* out = (float*)d_out;

    cudaFuncSetAttribute(k_scan_h2, cudaFuncAttributeMaxDynamicSharedMemorySize, SMEM_BYTES);

    k_init   <<<NROWS / 256, 256>>>();
    k_quant_x<<<NROWS / 8, 256>>>(lat);
    k_quant_c<<<(DDIM * KCB) / 256, 256>>>(cb);
    k_scan_h2<<<GRID_SCAN, 256, SMEM_BYTES>>>();
    k_exact  <<<NROWS / 8, 256>>>(lat, cb, out);
    k_gather <<<NROWS / 8, 256>>>(lat, mask, cb, out);
    k_final  <<<1, 256>>>(mask, out);
}

// round 12
// speedup vs baseline: 2.0656x; 2.0656x over previous
#include <cuda_runtime.h>
#include <math.h>
#include <stdint.h>

#define NROWS 16384
#define DDIM  256
#define KCB   8192

#define OFF_Q   16384
#define OFF_ST  (16384 + NROWS*DDIM)
#define OFF_SC  (16384 + 2*NROWS*DDIM)

#define SLOTS 64
#define EPS 5e-5f

#define TM   64                   // rows per rowblk
#define TKT  128                  // codebook cols per tile
#define DC   16                   // d per stage
#define KSLICE 1024
#define NRB  (NROWS / TM)         // 256
#define NSL  (KCB / KSLICE)       // 8
#define NUNITS (NRB * NSL)        // 2048
#define USTAGES 128               // 8 tiles x 16 d-chunks
#define GRID_SCAN 296

#define A_STRIDE 68               // words per d-row (64 rows + 4 pad), 272B (16B-aligned)
#define AW (DDIM * A_STRIDE)      // 17408 words
#define BW (DC * TKT)             // 2048 words per buffer
#define SMEM_WORDS (AW + 3 * BW + TM + 16)
#define SMEM_BYTES (SMEM_WORDS * 4)   // 94,592 B -> 2 CTAs/SM

__device__ float  d_xtT[(size_t)NROWS * DDIM];   // [rbi][d][row64] fp32
__device__ float  d_ctT[(size_t)DDIM * KCB];     // [d][col] fp32
__device__ float  d_hist[KCB];
__device__ int    d_bidx[NROWS];
__device__ int    d_cnt[NROWS];
__device__ int    d_cand[NROWS * SLOTS];
__device__ double d_sqsum;
__device__ int    d_wq;

// ---------------------------------------------------------------------------
// helpers
// ---------------------------------------------------------------------------
__device__ __forceinline__ uint32_t smem_u32(const void* p) {
    uint32_t a;
    asm("{ .reg .u64 t; cvta.to.shared.u64 t, %1; cvt.u32.u64 %0, t; }" : "=r"(a) : "l"(p));
    return a;
}
__device__ __forceinline__ void cp_async16(uint32_t dst, const void* src) {
    asm volatile("cp.async.cg.shared.global [%0], [%1], 16;" :: "r"(dst), "l"(src) : "memory");
}
#define CP_COMMIT() asm volatile("cp.async.commit_group;" ::: "memory")
#define CP_WAIT(n)  asm volatile("cp.async.wait_group %0;" :: "n"(n) : "memory")

__device__ __forceinline__ int   fmap(float f)  { int i = __float_as_int(f); return i < 0 ? i ^ 0x7FFFFFFF : i; }
__device__ __forceinline__ float funmap(int u)  { if (u < 0) u ^= 0x7FFFFFFF; return __int_as_float(u); }

__device__ __forceinline__ void fma2(unsigned long long& d, unsigned long long a,
                                     unsigned long long b) {
    asm("fma.rn.f32x2 %0, %1, %2, %0;" : "+l"(d) : "l"(a), "l"(b));
}
__device__ __forceinline__ unsigned long long pack_dup(float f) {
    unsigned long long o;
    unsigned u = __float_as_uint(f);
    asm("mov.b64 %0, {%1, %1};" : "=l"(o) : "r"(u));
    return o;
}
__device__ __forceinline__ void unpack2(unsigned long long v, float& lo, float& hi) {
    unsigned a, b;
    asm("mov.b64 {%0, %1}, %2;" : "=r"(a), "=r"(b) : "l"(v));
    lo = __uint_as_float(a); hi = __uint_as_float(b);
}

// ---------------------------------------------------------------------------
// Kernel 1: zero accumulators + work queue
// ---------------------------------------------------------------------------
__global__ void k_init() {
    int i = blockIdx.x * 256 + threadIdx.x;
    if (i < KCB)   d_hist[i] = 0.f;
    if (i < NROWS) d_cnt[i]  = 0;
    if (i == 0)  { d_sqsum   = 0.0; d_wq = 0; }
}

// ---------------------------------------------------------------------------
// Kernel 2a: pre-transpose latents -> [rbi][d][row64]  (coalesced writes)
// ---------------------------------------------------------------------------
__global__ __launch_bounds__(256) void k_prep_x(const float* __restrict__ lat) {
    int g = blockIdx.x * 256 + threadIdx.x;          // 4,194,304 elements
    int row = g & 63, d = (g >> 6) & 255, rbi = g >> 14;
    d_xtT[g] = lat[((size_t)(rbi * TM + row)) * DDIM + d];
}

// ---------------------------------------------------------------------------
// Kernel 2b: pre-transpose codebook -> [d][col]  (coalesced writes)
// ---------------------------------------------------------------------------
__global__ __launch_bounds__(256) void k_prep_c(const float* __restrict__ cb) {
    int g = blockIdx.x * 256 + threadIdx.x;          // 2,097,152 elements
    int col = g & (KCB - 1), d = g >> 13;
    d_ctT[g] = cb[(size_t)col * DDIM + d];
}

// ---------------------------------------------------------------------------
// Kernel 3: persistent work-queue FFMA2 scan, 2 CTAs/SM
// unit = 64 rows x 1024 codes; 256 threads (tx 16 col-groups, ty 16 row-groups)
// thread tile: 4 rows x 8 cols, col-packed f32x2 accumulators
// ---------------------------------------------------------------------------
#define ISSUE_B(s_) do {                                                        \
    int t_ = (s_) >> 4, c_ = (s_) & 15, buf_ = (s_) % 3;                        \
    const float* gB_ = d_ctT + (size_t)(c_ * DC) * KCB + ksl * KSLICE + t_ * TKT; \
    _Pragma("unroll")                                                           \
    for (int i_ = 0; i_ < 2; i_++) {                                            \
        int s2_ = tid + i_ * 256;                                               \
        int dd_ = s2_ >> 5, ch_ = s2_ & 31;                                     \
        cp_async16(sbB + (uint32_t)(buf_ * BW + dd_ * TKT + ch_ * 4) * 4,       \
                   gB_ + (size_t)dd_ * KCB + ch_ * 4);                          \
    }                                                                           \
    CP_COMMIT();                                                                \
} while (0)

__global__ __launch_bounds__(256, 2) void k_scan_f2() {
    extern __shared__ __align__(16) float smf[];
    float* As = smf;                        // [d][row] stride 68
    float* Bs = smf + AW;                   // 3 buffers [16 dd][128 col]
    int*   Rb = (int*)(smf + AW + 3 * BW);
    __shared__ int s_unit;

    const int tid = threadIdx.x;
    const int tx = tid & 15, ty = tid >> 4;
    const uint32_t sbA = smem_u32(As);
    const uint32_t sbB = smem_u32(Bs);

    for (;;) {
        if (tid == 0) s_unit = atomicAdd(&d_wq, 1);
        __syncthreads();                    // also fences prev unit's Rb readers
        const int u = s_unit;
        if (u >= NUNITS) break;
        const int rbi = u >> 3, ksl = u & 7;
        const int rowblk = rbi * TM;

        if (tid < TM) Rb[tid] = fmap(-3.0e38f);

        // issue A tile: exactly DDIM*TM/4 = 4096 16B chunks = 16 iterations
        {
            const float* gA = d_xtT + (size_t)rbi * (DDIM * TM);
#pragma unroll
            for (int i = 0; i < 16; i++) {
                int s2 = tid + i * 256;            // 0..4095
                int d = s2 >> 4, rg = s2 & 15;     // d in 0..255, rg in 0..15
                cp_async16(sbA + (uint32_t)(d * A_STRIDE + rg * 4) * 4,
                           gA + (size_t)d * TM + rg * 4);
            }
            CP_COMMIT();
        }
        ISSUE_B(0);
        ISSUE_B(1);

        unsigned long long acc[4][4];
#pragma unroll
        for (int r = 0; r < 4; r++)
#pragma unroll
            for (int j = 0; j < 4; j++) acc[r][j] = 0ull;

        for (int s = 0; s < USTAGES; s++) {
            const int c = s & 15, t = s >> 4;
            const float* B = Bs + (s % 3) * BW;
            if (s + 2 < USTAGES) { CP_WAIT(1); } else { CP_WAIT(0); }
            __syncthreads();
            if (s + 2 < USTAGES) ISSUE_B(s + 2);

#pragma unroll
            for (int dd = 0; dd < DC; dd++) {
                float4 af = *(const float4*)(As + (size_t)(c * DC + dd) * A_STRIDE + 4 * ty);
                unsigned long long a0 = pack_dup(af.x), a1 = pack_dup(af.y);
                unsigned long long a2 = pack_dup(af.z), a3 = pack_dup(af.w);
                const float* bp = B + (size_t)dd * TKT + 8 * tx;
                ulonglong2 b01 = *(const ulonglong2*)bp;        // cols +0..3 as 2 f32x2
                ulonglong2 b23 = *(const ulonglong2*)(bp + 4);  // cols +4..7
                fma2(acc[0][0], a0, b01.x); fma2(acc[1][0], a1, b01.x);
                fma2(acc[2][0], a2, b01.x); fma2(acc[3][0], a3, b01.x);
                fma2(acc[0][1], a0, b01.y); fma2(acc[1][1], a1, b01.y);
                fma2(acc[2][1], a2, b01.y); fma2(acc[3][1], a3, b01.y);
                fma2(acc[0][2], a0, b23.x); fma2(acc[1][2], a1, b23.x);
                fma2(acc[2][2], a2, b23.x); fma2(acc[3][2], a3, b23.x);
                fma2(acc[0][3], a0, b23.y); fma2(acc[1][3], a1, b23.y);
                fma2(acc[2][3], a2, b23.y); fma2(acc[3][3], a3, b23.y);
            }

            if (c == 15) {      // end of 128-col k-tile: max + collect + reset
                const int kbase = ksl * KSLICE + t * TKT;
                float vals[4][8];
#pragma unroll
                for (int r = 0; r < 4; r++)
#pragma unroll
                    for (int j = 0; j < 4; j++) {
                        unpack2(acc[r][j], vals[r][2 * j], vals[r][2 * j + 1]);
                        acc[r][j] = 0ull;
                    }
#pragma unroll
                for (int r = 0; r < 4; r++) {
                    float mx = vals[r][0];
#pragma unroll
                    for (int cc = 1; cc < 8; cc++) mx = fmaxf(mx, vals[r][cc]);
                    mx = fmaxf(mx, __shfl_xor_sync(0xffffffffu, mx, 1));
                    mx = fmaxf(mx, __shfl_xor_sync(0xffffffffu, mx, 2));
                    mx = fmaxf(mx, __shfl_xor_sync(0xffffffffu, mx, 4));
                    mx = fmaxf(mx, __shfl_xor_sync(0xffffffffu, mx, 8));
                    if (tx == 0) {
                        int mm = fmap(mx);
                        if (mm > Rb[4 * ty + r]) atomicMax(&Rb[4 * ty + r], mm);
                    }
                    // own tile max always in threshold; stale Rb reads only over-collect
                    const float thr = fmaxf(funmap(Rb[4 * ty + r]), mx) - EPS;
                    const int grow = rowblk + 4 * ty + r;
#pragma unroll
                    for (int cc = 0; cc < 8; cc++) {
                        if (vals[r][cc] > thr) {
                            int pos = atomicAdd(&d_cnt[grow], 1);
                            if (pos < SLOTS)
                                d_cand[grow * SLOTS + pos] = kbase + 8 * tx + cc;
                        }
                    }
                }
            }
        }
    }
}

// ---------------------------------------------------------------------------
// Kernel 4: exact re-evaluation of candidates, replicate reference rounding:
// q = fl( fl(xn2 + cn2) - 2*dot_f ), argmin with lowest-index ties.
// ---------------------------------------------------------------------------
__global__ __launch_bounds__(256) void k_exact(const float* __restrict__ lat,
                                               const float* __restrict__ cb,
                                               float* __restrict__ out) {
    const int tid = threadIdx.x;
    const int lane = tid & 31, w = tid >> 5;
    const int row = blockIdx.x * 8 + w;

    float x[8];
    {
        const float4* xr = (const float4*)(lat + (size_t)row * DDIM);
        float4 a = xr[lane * 2], b = xr[lane * 2 + 1];
        x[0]=a.x; x[1]=a.y; x[2]=a.z; x[3]=a.w;
        x[4]=b.x; x[5]=b.y; x[6]=b.z; x[7]=b.w;
    }
    double xs = 0.0;
#pragma unroll
    for (int i = 0; i < 8; i++) xs += (double)x[i] * (double)x[i];
#pragma unroll
    for (int o = 16; o; o >>= 1) xs += __shfl_xor_sync(0xffffffffu, xs, o);
    float xn2 = (float)xs;

    int   n     = d_cnt[row];
    bool  fallb = (n > SLOTS);
    int   ncand = fallb ? KCB : n;

    float bestq = 3.4e38f;
    int   besti = 0;

    for (int c = 0; c < ncand; c++) {
        int idx = fallb ? c : d_cand[row * SLOTS + c];
        const float4* cr = (const float4*)(cb + (size_t)idx * DDIM);
        float4 a = cr[lane * 2], b = cr[lane * 2 + 1];
        float cv[8] = {a.x, a.y, a.z, a.w, b.x, b.y, b.z, b.w};

        float hi = 0.f, co = 0.f, cn = 0.f;
#pragma unroll
        for (int i = 0; i < 8; i++) {
            float p = __fmul_rn(x[i], cv[i]);
            float e = __fmaf_rn(x[i], cv[i], -p);
            float t = __fadd_rn(hi, p);
            float z = __fsub_rn(t, hi);
            float q2 = __fadd_rn(__fsub_rn(hi, __fsub_rn(t, z)), __fsub_rn(p, z));
            hi = t; co = __fadd_rn(co, __fadd_rn(q2, e));
            cn = __fmaf_rn(cv[i], cv[i], cn);
        }
#pragma unroll
        for (int o = 16; o; o >>= 1) {
            float h2 = __shfl_xor_sync(0xffffffffu, hi, o);
            float c2 = __shfl_xor_sync(0xffffffffu, co, o);
            cn += __shfl_xor_sync(0xffffffffu, cn, o);
            float t = __fadd_rn(hi, h2);
            float z = __fsub_rn(t, hi);
            float q2 = __fadd_rn(__fsub_rn(hi, __fsub_rn(t, z)), __fsub_rn(h2, z));
            hi = t; co = __fadd_rn(co, __fadd_rn(c2, q2));
        }
        if (lane == 0) {
            float df = __fadd_rn(hi, co);
            float t1 = __fadd_rn(xn2, cn);
            float q  = __fadd_rn(t1, -__fmul_rn(2.f, df));
            if (q < bestq || (q == bestq && idx < besti)) { bestq = q; besti = idx; }
        }
    }
    if (lane == 0) {
        d_bidx[row] = besti;
        out[row] = (float)besti;
    }
}

// ---------------------------------------------------------------------------
// Kernel 5: gather -> quantized + st_quantized, MSE partials, histogram
// ---------------------------------------------------------------------------
__global__ __launch_bounds__(256) void k_gather(const float* __restrict__ lat,
                                                const float* __restrict__ mask,
                                                const float* __restrict__ cb,
                                                float* __restrict__ out) {
    __shared__ float wsum[8];
    const int tid = threadIdx.x;
    const int lane = tid & 31, w = tid >> 5;
    const int row = blockIdx.x * 8 + w;

    int idx = d_bidx[row];
    const float4* x = (const float4*)(lat + (size_t)row * DDIM);
    const float4* c = (const float4*)(cb + (size_t)idx * DDIM);
    float4* q  = (float4*)(out + OFF_Q  + (size_t)row * DDIM);
    float4* st = (float4*)(out + OFF_ST + (size_t)row * DDIM);

    float s = 0.f;
#pragma unroll
    for (int i = lane; i < DDIM / 4; i += 32) {
        float4 cv = c[i], xv = x[i];
        q[i]  = cv;
        st[i] = cv;
        float d0 = xv.x - cv.x, d1 = xv.y - cv.y;
        float d2 = xv.z - cv.z, d3 = xv.w - cv.w;
        s += d0 * d0 + d1 * d1 + d2 * d2 + d3 * d3;
    }
#pragma unroll
    for (int o = 16; o; o >>= 1) s += __shfl_xor_sync(0xffffffffu, s, o);
    if (lane == 0) {
        wsum[w] = s;
        atomicAdd(&d_hist[idx], mask[row]);
    }
    __syncthreads();
    if (tid == 0) {
        double t = 0.0;
#pragma unroll
        for (int i = 0; i < 8; i++) t += (double)wsum[i];
        atomicAdd(&d_sqsum, t);
    }
}

// ---------------------------------------------------------------------------
// Kernel 6: finalize losses + perplexity
// ---------------------------------------------------------------------------
__global__ void k_final(const float* __restrict__ mask, float* __restrict__ out) {
    __shared__ float sh[256];
    const int tid = threadIdx.x;

    float m = 0.f;
    for (int i = tid; i < NROWS; i += 256) m += mask[i];
    sh[tid] = m; __syncthreads();
    for (int o = 128; o; o >>= 1) { if (tid < o) sh[tid] += sh[tid + o]; __syncthreads(); }
    float denom = fmaxf(sh[0], 1.0f);
    __syncthreads();

    float e = 0.f;
    for (int k2 = tid; k2 < KCB; k2 += 256) {
        float p = d_hist[k2] / denom;
        e += p * logf(p + 1e-8f);
    }
    sh[tid] = e; __syncthreads();
    for (int o = 128; o; o >>= 1) { if (tid < o) sh[tid] += sh[tid + o]; __syncthreads(); }

    if (tid == 0) {
        double mse = d_sqsum / (double)((size_t)NROWS * DDIM);
        out[OFF_SC + 0] = (float)(mse * 0.25);
        out[OFF_SC + 1] = (float)mse;
        out[OFF_SC + 2] = expf(-sh[0]);
    }
}

// ---------------------------------------------------------------------------
extern "C" void kernel_launch(void* const* d_in, const int* in_sizes, int n_in,
                              void* d_out, int out_size) {
    const float* lat  = (const float*)d_in[0];
    const float* mask = (const float*)d_in[1];
    const float* cb   = (const float*)d_in[2];
    float* out = (float*)d_out;

    cudaFuncSetAttribute(k_scan_f2, cudaFuncAttributeMaxDynamicSharedMemorySize, SMEM_BYTES);

    k_init   <<<NROWS / 256, 256>>>();
    k_prep_x <<<(NROWS * DDIM) / 256, 256>>>(lat);
    k_prep_c <<<(DDIM * KCB) / 256, 256>>>(cb);
    k_scan_f2<<<GRID_SCAN, 256, SMEM_BYTES>>>();
    k_exact  <<<NROWS / 8, 256>>>(lat, cb, out);
    k_gather <<<NROWS / 8, 256>>>(lat, mask, cb, out);
    k_final  <<<1, 256>>>(mask, out);
}

// round 13
// speedup vs baseline: 3.1816x; 1.5403x over previous
#include <cuda_runtime.h>
#include <math.h>
#include <stdint.h>

#define NROWS 16384
#define DDIM  256
#define KCB   8192

#define OFF_Q   16384
#define OFF_ST  (16384 + NROWS*DDIM)
#define OFF_SC  (16384 + 2*NROWS*DDIM)

#define SLOTS 64
#define EPS 5e-5f

#define TM   64                   // rows per rowblk
#define TKT  128                  // codebook cols per tile
#define DC   16                   // d per stage
#define KSLICE 1024
#define NRB  (NROWS / TM)         // 256
#define NSL  (KCB / KSLICE)       // 8
#define NUNITS (NRB * NSL)        // 2048
#define USTAGES 128               // 8 tiles x 16 d-chunks
#define GRID_SCAN 296

#define A_STRIDE 68               // words per d-row (64 rows + 4 pad), 272B (16B-aligned)
#define AW (DDIM * A_STRIDE)      // 17408 words
#define BW (DC * TKT)             // 2048 words per buffer
#define SMEM_WORDS (AW + 3 * BW + TM + 16)
#define SMEM_BYTES (SMEM_WORDS * 4)   // 94,592 B -> 2 CTAs/SM

__device__ float  d_xtT[(size_t)NROWS * DDIM];   // [rbi][d][row64] fp32
__device__ float  d_ctT[(size_t)DDIM * KCB];     // [d][col] fp32
__device__ float  d_hist[KCB];
__device__ int    d_bidx[NROWS];
__device__ int    d_cnt[NROWS];
__device__ int    d_cand[NROWS * SLOTS];
__device__ double d_sqsum;
__device__ int    d_wq;

// ---------------------------------------------------------------------------
// helpers
// ---------------------------------------------------------------------------
__device__ __forceinline__ uint32_t smem_u32(const void* p) {
    uint32_t a;
    asm("{ .reg .u64 t; cvta.to.shared.u64 t, %1; cvt.u32.u64 %0, t; }" : "=r"(a) : "l"(p));
    return a;
}
__device__ __forceinline__ void cp_async16(uint32_t dst, const void* src) {
    asm volatile("cp.async.cg.shared.global [%0], [%1], 16;" :: "r"(dst), "l"(src) : "memory");
}
#define CP_COMMIT() asm volatile("cp.async.commit_group;" ::: "memory")
#define CP_WAIT(n)  asm volatile("cp.async.wait_group %0;" :: "n"(n) : "memory")

__device__ __forceinline__ int   fmap(float f)  { int i = __float_as_int(f); return i < 0 ? i ^ 0x7FFFFFFF : i; }
__device__ __forceinline__ float funmap(int u)  { if (u < 0) u ^= 0x7FFFFFFF; return __int_as_float(u); }

__device__ __forceinline__ void fma2(unsigned long long& d, unsigned long long a,
                                     unsigned long long b) {
    asm("fma.rn.f32x2 %0, %1, %2, %0;" : "+l"(d) : "l"(a), "l"(b));
}
__device__ __forceinline__ unsigned long long pack_dup(float f) {
    unsigned long long o;
    unsigned u = __float_as_uint(f);
    asm("mov.b64 %0, {%1, %1};" : "=l"(o) : "r"(u));
    return o;
}
__device__ __forceinline__ void unpack2(unsigned long long v, float& lo, float& hi) {
    unsigned a, b;
    asm("mov.b64 {%0, %1}, %2;" : "=r"(a), "=r"(b) : "l"(v));
    lo = __uint_as_float(a); hi = __uint_as_float(b);
}

// ---------------------------------------------------------------------------
// Kernel 1: zero accumulators + work queue
// ---------------------------------------------------------------------------
__global__ void k_init() {
    int i = blockIdx.x * 256 + threadIdx.x;
    if (i < KCB)   d_hist[i] = 0.f;
    if (i < NROWS) d_cnt[i]  = 0;
    if (i == 0)  { d_sqsum   = 0.0; d_wq = 0; }
}

// ---------------------------------------------------------------------------
// Kernel 2a: pre-transpose latents -> [rbi][d][row64]  (coalesced writes)
// ---------------------------------------------------------------------------
__global__ __launch_bounds__(256) void k_prep_x(const float* __restrict__ lat) {
    int g = blockIdx.x * 256 + threadIdx.x;          // 4,194,304 elements
    int row = g & 63, d = (g >> 6) & 255, rbi = g >> 14;
    d_xtT[g] = lat[((size_t)(rbi * TM + row)) * DDIM + d];
}

// ---------------------------------------------------------------------------
// Kernel 2b: pre-transpose codebook -> [d][col]  (coalesced writes)
// ---------------------------------------------------------------------------
__global__ __launch_bounds__(256) void k_prep_c(const float* __restrict__ cb) {
    int g = blockIdx.x * 256 + threadIdx.x;          // 2,097,152 elements
    int col = g & (KCB - 1), d = g >> 13;
    d_ctT[g] = cb[(size_t)col * DDIM + d];
}

// ---------------------------------------------------------------------------
// Kernel 3: persistent work-queue FFMA2 scan, 2 CTAs/SM
// unit = 64 rows x 1024 codes; 256 threads (tx 16 col-groups, ty 16 row-groups)
// thread tile: 4 rows x 8 cols (two 4-col groups 64 apart -> conflict-free LDS)
// ---------------------------------------------------------------------------
#define ISSUE_B(s_) do {                                                        \
    int t_ = (s_) >> 4, c_ = (s_) & 15, buf_ = (s_) % 3;                        \
    const float* gB_ = d_ctT + (size_t)(c_ * DC) * KCB + ksl * KSLICE + t_ * TKT; \
    _Pragma("unroll")                                                           \
    for (int i_ = 0; i_ < 2; i_++) {                                            \
        int s2_ = tid + i_ * 256;                                               \
        int dd_ = s2_ >> 5, ch_ = s2_ & 31;                                     \
        cp_async16(sbB + (uint32_t)(buf_ * BW + dd_ * TKT + ch_ * 4) * 4,       \
                   gB_ + (size_t)dd_ * KCB + ch_ * 4);                          \
    }                                                                           \
    CP_COMMIT();                                                                \
} while (0)

__global__ __launch_bounds__(256, 2) void k_scan_f2() {
    extern __shared__ __align__(16) float smf[];
    float* As = smf;                        // [d][row] stride 68
    float* Bs = smf + AW;                   // 3 buffers [16 dd][128 col]
    int*   Rb = (int*)(smf + AW + 3 * BW);
    __shared__ int s_unit;

    const int tid = threadIdx.x;
    const int tx = tid & 15, ty = tid >> 4;
    const uint32_t sbA = smem_u32(As);
    const uint32_t sbB = smem_u32(Bs);

    for (;;) {
        if (tid == 0) s_unit = atomicAdd(&d_wq, 1);
        __syncthreads();                    // also fences prev unit's Rb readers
        const int u = s_unit;
        if (u >= NUNITS) break;
        const int rbi = u >> 3, ksl = u & 7;
        const int rowblk = rbi * TM;

        if (tid < TM) Rb[tid] = fmap(-3.0e38f);

        // issue A tile: exactly DDIM*TM/4 = 4096 16B chunks = 16 iterations
        {
            const float* gA = d_xtT + (size_t)rbi * (DDIM * TM);
#pragma unroll
            for (int i = 0; i < 16; i++) {
                int s2 = tid + i * 256;            // 0..4095
                int d = s2 >> 4, rg = s2 & 15;     // d in 0..255, rg in 0..15
                cp_async16(sbA + (uint32_t)(d * A_STRIDE + rg * 4) * 4,
                           gA + (size_t)d * TM + rg * 4);
            }
            CP_COMMIT();
        }
        ISSUE_B(0);
        ISSUE_B(1);

        unsigned long long acc[4][4];
#pragma unroll
        for (int r = 0; r < 4; r++)
#pragma unroll
            for (int j = 0; j < 4; j++) acc[r][j] = 0ull;

        for (int s = 0; s < USTAGES; s++) {
            const int c = s & 15, t = s >> 4;
            const float* B = Bs + (s % 3) * BW;
            if (s + 2 < USTAGES) { CP_WAIT(1); } else { CP_WAIT(0); }
            __syncthreads();
            if (s + 2 < USTAGES) ISSUE_B(s + 2);

#pragma unroll
            for (int dd = 0; dd < DC; dd++) {
                float4 af = *(const float4*)(As + (size_t)(c * DC + dd) * A_STRIDE + 4 * ty);
                unsigned long long a0 = pack_dup(af.x), a1 = pack_dup(af.y);
                unsigned long long a2 = pack_dup(af.z), a3 = pack_dup(af.w);
                // two 16B B loads at 16B lane stride (2-wavefront minimum, no
                // 4-way conflict): cols [4tx..4tx+3] and [64+4tx..64+4tx+3]
                const float* bp = B + (size_t)dd * TKT;
                ulonglong2 b01 = *(const ulonglong2*)(bp + 4 * tx);
                ulonglong2 b23 = *(const ulonglong2*)(bp + 64 + 4 * tx);
                fma2(acc[0][0], a0, b01.x); fma2(acc[1][0], a1, b01.x);
                fma2(acc[2][0], a2, b01.x); fma2(acc[3][0], a3, b01.x);
                fma2(acc[0][1], a0, b01.y); fma2(acc[1][1], a1, b01.y);
                fma2(acc[2][1], a2, b01.y); fma2(acc[3][1], a3, b01.y);
                fma2(acc[0][2], a0, b23.x); fma2(acc[1][2], a1, b23.x);
                fma2(acc[2][2], a2, b23.x); fma2(acc[3][2], a3, b23.x);
                fma2(acc[0][3], a0, b23.y); fma2(acc[1][3], a1, b23.y);
                fma2(acc[2][3], a2, b23.y); fma2(acc[3][3], a3, b23.y);
            }

            if (c == 15) {      // end of 128-col k-tile: max + collect + reset
                const int kbase = ksl * KSLICE + t * TKT;
                float vals[4][8];
#pragma unroll
                for (int r = 0; r < 4; r++)
#pragma unroll
                    for (int j = 0; j < 4; j++) {
                        unpack2(acc[r][j], vals[r][2 * j], vals[r][2 * j + 1]);
                        acc[r][j] = 0ull;
                    }
#pragma unroll
                for (int r = 0; r < 4; r++) {
                    float mx = vals[r][0];
#pragma unroll
                    for (int cc = 1; cc < 8; cc++) mx = fmaxf(mx, vals[r][cc]);
                    mx = fmaxf(mx, __shfl_xor_sync(0xffffffffu, mx, 1));
                    mx = fmaxf(mx, __shfl_xor_sync(0xffffffffu, mx, 2));
                    mx = fmaxf(mx, __shfl_xor_sync(0xffffffffu, mx, 4));
                    mx = fmaxf(mx, __shfl_xor_sync(0xffffffffu, mx, 8));
                    if (tx == 0) {
                        int mm = fmap(mx);
                        if (mm > Rb[4 * ty + r]) atomicMax(&Rb[4 * ty + r], mm);
                    }
                    // own tile max always in threshold; stale Rb reads only over-collect
                    const float thr = fmaxf(funmap(Rb[4 * ty + r]), mx) - EPS;
                    const int grow = rowblk + 4 * ty + r;
#pragma unroll
                    for (int cc = 0; cc < 8; cc++) {
                        if (vals[r][cc] > thr) {
                            int pos = atomicAdd(&d_cnt[grow], 1);
                            int col = (cc < 4) ? (kbase + 4 * tx + cc)
                                               : (kbase + 64 + 4 * tx + (cc - 4));
                            if (pos < SLOTS)
                                d_cand[grow * SLOTS + pos] = col;
                        }
                    }
                }
            }
        }
    }
}

// ---------------------------------------------------------------------------
// Kernel 4: exact re-evaluation of candidates, replicate reference rounding:
// q = fl( fl(xn2 + cn2) - 2*dot_f ), argmin with lowest-index ties.
// ---------------------------------------------------------------------------
__global__ __launch_bounds__(256) void k_exact(const float* __restrict__ lat,
                                               const float* __restrict__ cb,
                                               float* __restrict__ out) {
    const int tid = threadIdx.x;
    const int lane = tid & 31, w = tid >> 5;
    const int row = blockIdx.x * 8 + w;

    float x[8];
    {
        const float4* xr = (const float4*)(lat + (size_t)row * DDIM);
        float4 a = xr[lane * 2], b = xr[lane * 2 + 1];
        x[0]=a.x; x[1]=a.y; x[2]=a.z; x[3]=a.w;
        x[4]=b.x; x[5]=b.y; x[6]=b.z; x[7]=b.w;
    }
    double xs = 0.0;
#pragma unroll
    for (int i = 0; i < 8; i++) xs += (double)x[i] * (double)x[i];
#pragma unroll
    for (int o = 16; o; o >>= 1) xs += __shfl_xor_sync(0xffffffffu, xs, o);
    float xn2 = (float)xs;

    int   n     = d_cnt[row];
    bool  fallb = (n > SLOTS);
    int   ncand = fallb ? KCB : n;

    float bestq = 3.4e38f;
    int   besti = 0;

    for (int c = 0; c < ncand; c++) {
        int idx = fallb ? c : d_cand[row * SLOTS + c];
        const float4* cr = (const float4*)(cb + (size_t)idx * DDIM);
        float4 a = cr[lane * 2], b = cr[lane * 2 + 1];
        float cv[8] = {a.x, a.y, a.z, a.w, b.x, b.y, b.z, b.w};

        float hi = 0.f, co = 0.f, cn = 0.f;
#pragma unroll
        for (int i = 0; i < 8; i++) {
            float p = __fmul_rn(x[i], cv[i]);
            float e = __fmaf_rn(x[i], cv[i], -p);
            float t = __fadd_rn(hi, p);
            float z = __fsub_rn(t, hi);
            float q2 = __fadd_rn(__fsub_rn(hi, __fsub_rn(t, z)), __fsub_rn(p, z));
            hi = t; co = __fadd_rn(co, __fadd_rn(q2, e));
            cn = __fmaf_rn(cv[i], cv[i], cn);
        }
#pragma unroll
        for (int o = 16; o; o >>= 1) {
            float h2 = __shfl_xor_sync(0xffffffffu, hi, o);
            float c2 = __shfl_xor_sync(0xffffffffu, co, o);
            cn += __shfl_xor_sync(0xffffffffu, cn, o);
            float t = __fadd_rn(hi, h2);
            float z = __fsub_rn(t, hi);
            float q2 = __fadd_rn(__fsub_rn(hi, __fsub_rn(t, z)), __fsub_rn(h2, z));
            hi = t; co = __fadd_rn(co, __fadd_rn(c2, q2));
        }
        if (lane == 0) {
            float df = __fadd_rn(hi, co);
            float t1 = __fadd_rn(xn2, cn);
            float q  = __fadd_rn(t1, -__fmul_rn(2.f, df));
            if (q < bestq || (q == bestq && idx < besti)) { bestq = q; besti = idx; }
        }
    }
    if (lane == 0) {
        d_bidx[row] = besti;
        out[row] = (float)besti;
    }
}

// ---------------------------------------------------------------------------
// Kernel 5: gather -> quantized + st_quantized, MSE partials, histogram
// ---------------------------------------------------------------------------
__global__ __launch_bounds__(256) void k_gather(const float* __restrict__ lat,
                                                const float* __restrict__ mask,
                                                const float* __restrict__ cb,
                                                float* __restrict__ out) {
    __shared__ float wsum[8];
    const int tid = threadIdx.x;
    const int lane = tid & 31, w = tid >> 5;
    const int row = blockIdx.x * 8 + w;

    int idx = d_bidx[row];
    const float4* x = (const float4*)(lat + (size_t)row * DDIM);
    const float4* c = (const float4*)(cb + (size_t)idx * DDIM);
    float4* q  = (float4*)(out + OFF_Q  + (size_t)row * DDIM);
    float4* st = (float4*)(out + OFF_ST + (size_t)row * DDIM);

    float s = 0.f;
#pragma unroll
    for (int i = lane; i < DDIM / 4; i += 32) {
        float4 cv = c[i], xv = x[i];
        q[i]  = cv;
        st[i] = cv;
        float d0 = xv.x - cv.x, d1 = xv.y - cv.y;
        float d2 = xv.z - cv.z, d3 = xv.w - cv.w;
        s += d0 * d0 + d1 * d1 + d2 * d2 + d3 * d3;
    }
#pragma unroll
    for (int o = 16; o; o >>= 1) s += __shfl_xor_sync(0xffffffffu, s, o);
    if (lane == 0) {
        wsum[w] = s;
        atomicAdd(&d_hist[idx], mask[row]);
    }
    __syncthreads();
    if (tid == 0) {
        double t = 0.0;
#pragma unroll
        for (int i = 0; i < 8; i++) t += (double)wsum[i];
        atomicAdd(&d_sqsum, t);
    }
}

// ---------------------------------------------------------------------------
// Kernel 6: finalize losses + perplexity
// ---------------------------------------------------------------------------
__global__ void k_final(const float* __restrict__ mask, float* __restrict__ out) {
    __shared__ float sh[256];
    const int tid = threadIdx.x;

    float m = 0.f;
    for (int i = tid; i < NROWS; i += 256) m += mask[i];
    sh[tid] = m; __syncthreads();
    for (int o = 128; o; o >>= 1) { if (tid < o) sh[tid] += sh[tid + o]; __syncthreads(); }
    float denom = fmaxf(sh[0], 1.0f);
    __syncthreads();

    float e = 0.f;
    for (int k2 = tid; k2 < KCB; k2 += 256) {
        float p = d_hist[k2] / denom;
        e += p * logf(p + 1e-8f);
    }
    sh[tid] = e; __syncthreads();
    for (int o = 128; o; o >>= 1) { if (tid < o) sh[tid] += sh[tid + o]; __syncthreads(); }

    if (tid == 0) {
        double mse = d_sqsum / (double)((size_t)NROWS * DDIM);
        out[OFF_SC + 0] = (float)(mse * 0.25);
        out[OFF_SC + 1] = (float)mse;
        out[OFF_SC + 2] = expf(-sh[0]);
    }
}

// ---------------------------------------------------------------------------
extern "C" void kernel_launch(void* const* d_in, const int* in_sizes, int n_in,
                              void* d_out, int out_size) {
    const float* lat  = (const float*)d_in[0];
    const float* mask = (const float*)d_in[1];
    const float* cb   = (const float*)d_in[2];
    float* out = (float*)d_out;

    cudaFuncSetAttribute(k_scan_f2, cudaFuncAttributeMaxDynamicSharedMemorySize, SMEM_BYTES);

    k_init   <<<NROWS / 256, 256>>>();
    k_prep_x <<<(NROWS * DDIM) / 256, 256>>>(lat);
    k_prep_c <<<(DDIM * KCB) / 256, 256>>>(cb);
    k_scan_f2<<<GRID_SCAN, 256, SMEM_BYTES>>>();
    k_exact  <<<NROWS / 8, 256>>>(lat, cb, out);
    k_gather <<<NROWS / 8, 256>>>(lat, mask, cb, out);
    k_final  <<<1, 256>>>(mask, out);
}